// round 10
// baseline (speedup 1.0000x reference)
#include <cuda_runtime.h>
#include <cuda_bf16.h>
#include <cuda_fp16.h>
#include <math.h>

#define Bc 2
#define NH 6
#define HD 32
#define Dz 16
#define Hy 32
#define Wx 32
#define NS (Dz*Hy*Wx)      // 16384
#define CH 192
#define SCALE 0.17677669529663687f
#define AW 4               // warps per attention block

// Output regions (tuple concat): out, offs, offset_mag, branch_energy, guide
#define O_OUT   0
#define O_OFFS  6291456     // 2*192*16384
#define O_MAG   6881280     // + 2*6*16384*3
#define O_EN    6881292
#define O_GUIDE 6881296

// Scratch (device globals; allocation-free)
__device__ float   g_qT[Bc*NH*NS*HD];      // [bh][s][hd]
__device__ __half2 g_kvh[Bc*NH*NS*HD];     // [bh][s][hd] -> (k, v) fp16
__device__ float   g_tT[Bc*NH*NS*HD];
__device__ float   g_lepeT[Bc*NH*NS*HD];
__device__ float   g_attnC[Bc*CH*NS];      // [b][c][s]  (attn + lepe)
__device__ float   g_offs[Bc*NH*NS*3];
__device__ float   g_mag[Bc*NH];
__device__ float   g_energy[Bc*2];

__device__ __forceinline__ float warpSum(float v) {
#pragma unroll
    for (int o = 16; o; o >>= 1) v += __shfl_xor_sync(0xffffffffu, v, o);
    return v;
}

__global__ void k_zero() {
    int t = threadIdx.x;
    if (t < Bc*NH) g_mag[t] = 0.f;
    if (t < Bc*2)  g_energy[t] = 0.f;
}

// ================= GEMM: q conv  X[b,c,s] x qw -> g_qT [bh][s][hd] =================
// tile: 64 out x 128 s, 256 threads, per-thread 4o x 8s
__global__ __launch_bounds__(256) void k_gemm_q(const float* __restrict__ X,
                                                const float* __restrict__ W,
                                                const float* __restrict__ bias)
{
    const int b  = blockIdx.z;
    const int o0 = blockIdx.y * 64;
    const int s0 = blockIdx.x * 128;
    const int tid = threadIdx.x;
    const int tx = tid & 15, ty = tid >> 4;

    __shared__ __align__(16) float sW[16][68];    // [c][o]
    __shared__ __align__(16) float sX[16][136];   // [c][s]
    __shared__ float sC[64][129];

    float acc[4][8] = {};
    const float* Xb = X + (size_t)b * CH * NS;

    for (int kk = 0; kk < CH; kk += 16) {
        {
            int r = tid >> 2, cq = (tid & 3) * 4;
            float4 w4 = *(const float4*)&W[(o0 + r) * CH + kk + cq];
            sW[cq + 0][r] = w4.x; sW[cq + 1][r] = w4.y;
            sW[cq + 2][r] = w4.z; sW[cq + 3][r] = w4.w;
        }
        {
            int r = tid >> 4, sq = (tid & 15) * 8;
            *(float4*)&sX[r][sq]     = *(const float4*)&Xb[(size_t)(kk + r) * NS + s0 + sq];
            *(float4*)&sX[r][sq + 4] = *(const float4*)&Xb[(size_t)(kk + r) * NS + s0 + sq + 4];
        }
        __syncthreads();
#pragma unroll
        for (int k = 0; k < 16; k++) {
            float4 a  = *(const float4*)&sW[k][ty * 4];
            float4 b0 = *(const float4*)&sX[k][tx * 8];
            float4 b1 = *(const float4*)&sX[k][tx * 8 + 4];
            float av[4] = {a.x, a.y, a.z, a.w};
            float bv[8] = {b0.x, b0.y, b0.z, b0.w, b1.x, b1.y, b1.z, b1.w};
#pragma unroll
            for (int i = 0; i < 4; i++)
#pragma unroll
                for (int j = 0; j < 8; j++) acc[i][j] += av[i] * bv[j];
        }
        __syncthreads();
    }
#pragma unroll
    for (int i = 0; i < 4; i++) {
        float bv = bias[o0 + ty * 4 + i];
#pragma unroll
        for (int j = 0; j < 8; j++) sC[ty * 4 + i][tx * 8 + j] = acc[i][j] + bv;
    }
    __syncthreads();
#pragma unroll
    for (int it = 0; it < 32; ++it) {
        int idx = tid + it * 256;
        int ol = idx & 63, sl = idx >> 6;
        int o = o0 + ol;
        g_qT[(((size_t)b * NH + (o >> 5)) * NS + (s0 + sl)) * HD + (o & 31)] = sC[ol][sl];
    }
}

// ================= GEMM: fused k & v conv -> g_kvh half2 =================
__global__ __launch_bounds__(256) void k_gemm_kv(const float* __restrict__ X,
                                                 const float* __restrict__ Wk, const float* __restrict__ bk,
                                                 const float* __restrict__ Wv, const float* __restrict__ bv_)
{
    const int b  = blockIdx.z;
    const int o0 = blockIdx.y * 64;
    const int s0 = blockIdx.x * 128;
    const int tid = threadIdx.x;
    const int tx = tid & 15, ty = tid >> 4;

    __shared__ __align__(16) float sWk[16][68];
    __shared__ __align__(16) float sWv[16][68];
    __shared__ __align__(16) float sX[16][136];
    __shared__ __half2 sC2[64][133];

    float ak[4][8] = {}, av_[4][8] = {};
    const float* Xb = X + (size_t)b * CH * NS;

    for (int kk = 0; kk < CH; kk += 16) {
        {
            int r = tid >> 2, cq = (tid & 3) * 4;
            float4 w4 = *(const float4*)&Wk[(o0 + r) * CH + kk + cq];
            sWk[cq + 0][r] = w4.x; sWk[cq + 1][r] = w4.y; sWk[cq + 2][r] = w4.z; sWk[cq + 3][r] = w4.w;
            float4 v4 = *(const float4*)&Wv[(o0 + r) * CH + kk + cq];
            sWv[cq + 0][r] = v4.x; sWv[cq + 1][r] = v4.y; sWv[cq + 2][r] = v4.z; sWv[cq + 3][r] = v4.w;
        }
        {
            int r = tid >> 4, sq = (tid & 15) * 8;
            *(float4*)&sX[r][sq]     = *(const float4*)&Xb[(size_t)(kk + r) * NS + s0 + sq];
            *(float4*)&sX[r][sq + 4] = *(const float4*)&Xb[(size_t)(kk + r) * NS + s0 + sq + 4];
        }
        __syncthreads();
#pragma unroll
        for (int k = 0; k < 16; k++) {
            float4 wa = *(const float4*)&sWk[k][ty * 4];
            float4 wb = *(const float4*)&sWv[k][ty * 4];
            float4 b0 = *(const float4*)&sX[k][tx * 8];
            float4 b1 = *(const float4*)&sX[k][tx * 8 + 4];
            float wav[4] = {wa.x, wa.y, wa.z, wa.w};
            float wbv[4] = {wb.x, wb.y, wb.z, wb.w};
            float xv[8] = {b0.x, b0.y, b0.z, b0.w, b1.x, b1.y, b1.z, b1.w};
#pragma unroll
            for (int i = 0; i < 4; i++)
#pragma unroll
                for (int j = 0; j < 8; j++) {
                    ak[i][j]  += wav[i] * xv[j];
                    av_[i][j] += wbv[i] * xv[j];
                }
        }
        __syncthreads();
    }
#pragma unroll
    for (int i = 0; i < 4; i++) {
        int o = o0 + ty * 4 + i;
        float bkk = bk[o], bvv = bv_[o];
#pragma unroll
        for (int j = 0; j < 8; j++)
            sC2[ty * 4 + i][tx * 8 + j] = __floats2half2_rn(ak[i][j] + bkk, av_[i][j] + bvv);
    }
    __syncthreads();
#pragma unroll
    for (int it = 0; it < 32; ++it) {
        int idx = tid + it * 256;
        int ol = idx & 63, sl = idx >> 6;
        int o = o0 + ol;
        g_kvh[(((size_t)b * NH + (o >> 5)) * NS + (s0 + sl)) * HD + (o & 31)] = sC2[ol][sl];
    }
}

// ================= depthwise 3x3x3 on qT -> tT & lepeT (x-register-blocked) =================
__global__ __launch_bounds__(256) void k_dwconv(const float* __restrict__ odw, const float* __restrict__ odb,
                                                const float* __restrict__ rpew, const float* __restrict__ rpeb)
{
    const int bh = blockIdx.y;
    const int h = bh % NH;
    const int lane = threadIdx.x & 31, wid = threadIdx.x >> 5;

    __shared__ float sWt[27][32];
    __shared__ float sWl[27][32];
    for (int idx = threadIdx.x; idx < 27 * 32; idx += 256) {
        int c = idx & 31, tap = idx >> 5;
        sWt[tap][c] = odw[(h * 32 + c) * 27 + tap];
        sWl[tap][c] = rpew[(h * 32 + c) * 27 + tap];
    }
    __syncthreads();

    const float bt = odb[h * 32 + lane];
    const float bl = rpeb[h * 32 + lane];
    const float* base = g_qT + (size_t)bh * NS * HD;

    const int s0 = blockIdx.x * 64 + wid * 8;
    const int z = s0 >> 10, y = (s0 >> 5) & 31, xb = s0 & 31;

    float at[8], al[8];
#pragma unroll
    for (int p = 0; p < 8; p++) { at[p] = bt; al[p] = bl; }

#pragma unroll
    for (int kd = 0; kd < 3; kd++) {
        int zz = z + kd - 1;
        if ((unsigned)zz >= (unsigned)Dz) continue;
#pragma unroll
        for (int kh = 0; kh < 3; kh++) {
            int yy = y + kh - 1;
            if ((unsigned)yy >= (unsigned)Hy) continue;
            const float* rowp = base + (size_t)(zz * 1024 + yy * 32) * 32 + lane;
            float w[10];
#pragma unroll
            for (int i = 0; i < 10; i++) {
                int xx = xb - 1 + i;
                w[i] = ((unsigned)xx < (unsigned)Wx) ? rowp[xx * 32] : 0.f;
            }
            const int t0 = (kd * 3 + kh) * 3;
            const float wt0 = sWt[t0][lane], wt1 = sWt[t0 + 1][lane], wt2 = sWt[t0 + 2][lane];
            const float wl0 = sWl[t0][lane], wl1 = sWl[t0 + 1][lane], wl2 = sWl[t0 + 2][lane];
#pragma unroll
            for (int p = 0; p < 8; p++) {
                at[p] += w[p] * wt0 + w[p + 1] * wt1 + w[p + 2] * wt2;
                al[p] += w[p] * wl0 + w[p + 1] * wl1 + w[p + 2] * wl2;
            }
        }
    }
#pragma unroll
    for (int p = 0; p < 8; p++) {
        size_t oi = ((size_t)bh * NS + s0 + p) * 32 + lane;
        g_tT[oi] = at[p];
        g_lepeT[oi] = al[p];
    }
}

// ================= LN + GELU + offset conv + tanh*scale =================
__global__ void k_offsets(const float* __restrict__ lnw, const float* __restrict__ lnb,
                          const float* __restrict__ opw, const float* __restrict__ opb,
                          float* __restrict__ d_out)
{
    __shared__ float sOp[18 * 192];
    __shared__ float sLn[2][192];
    for (int i = threadIdx.x; i < 18 * 192; i += 256) sOp[i] = opw[i];
    for (int i = threadIdx.x; i < 192; i += 256) { sLn[0][i] = lnw[i]; sLn[1][i] = lnb[i]; }
    __syncthreads();

    const int lane = threadIdx.x & 31, wid = threadIdx.x >> 5;
    const int gid = blockIdx.x * 8 + wid;
    const int b = gid >> 14;
    const int s = gid & (NS - 1);

    float v[6];
#pragma unroll
    for (int h = 0; h < 6; h++) v[h] = g_tT[(((size_t)b * 6 + h) * NS + s) * 32 + lane];

    float sm = 0.f;
#pragma unroll
    for (int h = 0; h < 6; h++) sm += v[h];
    sm = warpSum(sm);
    float mean = sm * (1.f / 192.f);
    float s2 = 0.f;
#pragma unroll
    for (int h = 0; h < 6; h++) { float d = v[h] - mean; s2 += d * d; }
    s2 = warpSum(s2);
    float inv = rsqrtf(s2 * (1.f / 192.f) + 1e-5f);

    float g[6];
#pragma unroll
    for (int h = 0; h < 6; h++) {
        int c = h * 32 + lane;
        float n = (v[h] - mean) * inv * sLn[0][c] + sLn[1][c];
        g[h] = 0.5f * n * (1.f + erff(n * 0.70710678118654752f));
    }

    float p18[18];
#pragma unroll
    for (int o = 0; o < 18; o++) {
        float p = 0.f;
#pragma unroll
        for (int h = 0; h < 6; h++) p += g[h] * sOp[o * 192 + h * 32 + lane];
        p18[o] = p;
    }
#pragma unroll
    for (int o = 16; o; o >>= 1)
#pragma unroll
        for (int j = 0; j < 18; j++) p18[j] += __shfl_xor_sync(0xffffffffu, p18[j], o);

    float mine = 0.f;
#pragma unroll
    for (int j = 0; j < 18; j++) if (lane == j) mine = p18[j];

    float ov = 0.f;
    if (lane < 18) {
        float val = tanhf(mine + opb[lane]);
        int comp = lane % 3;
        float sc = (comp == 2) ? (2.f / 15.f) : (2.f / 31.f);
        ov = val * sc;
        int h = lane / 3;
        size_t oi = (((size_t)b * 6 + h) * NS + s) * 3 + comp;
        g_offs[oi] = ov;
        d_out[O_OFFS + oi] = ov;
    }
    float ox = __shfl_sync(0xffffffffu, ov, (lane < 6) ? 3 * lane : 0);
    float oy = __shfl_sync(0xffffffffu, ov, (lane < 6) ? 3 * lane + 1 : 0);
    float oz = __shfl_sync(0xffffffffu, ov, (lane < 6) ? 3 * lane + 2 : 0);
    if (lane < 6) atomicAdd(&g_mag[b * 6 + lane], sqrtf(ox * ox + oy * oy + oz * oz));
}

// ================= attention epilogue (AW warps) =================
__device__ __forceinline__ void attn_epilogue(float res, int b, int h, int bi,
                                              int lane, int wid, int s0b, size_t qi)
{
    float outv = res + g_lepeT[qi];
    __shared__ float sT[AW][33];
    __shared__ float sE[AW];
    sT[wid][lane] = outv;
    float e = warpSum(fabsf(res));
    if (lane == 0) sE[wid] = e;
    __syncthreads();
    int ch = threadIdx.x >> 2, si = threadIdx.x & 3;
    g_attnC[((size_t)b * CH + h * 32 + ch) * NS + s0b + si] = sT[si][ch];
    if (threadIdx.x == 0) {
        float t = 0.f;
#pragma unroll
        for (int i = 0; i < AW; i++) t += sE[i];
        atomicAdd(&g_energy[b * 2 + bi], t);
    }
}

// xy-lerped plane for attn1 (4x4 lattice, overlapping pairs)
__device__ __forceinline__ void plane4(const __half2* __restrict__ kv, int zoff,
                                       const int* LYo, const int* LXo,
                                       float wx, float wy, float2* out9)
{
    float2 Ap[3];
#pragma unroll
    for (int ty = 0; ty < 4; ty++) {
        float2 p0 = __half22float2(kv[zoff + LYo[ty] + LXo[0]]);
        float2 p1 = __half22float2(kv[zoff + LYo[ty] + LXo[1]]);
        float2 p2 = __half22float2(kv[zoff + LYo[ty] + LXo[2]]);
        float2 p3 = __half22float2(kv[zoff + LYo[ty] + LXo[3]]);
        float2 A[3];
        A[0].x = p0.x + wx * (p1.x - p0.x); A[0].y = p0.y + wx * (p1.y - p0.y);
        A[1].x = p1.x + wx * (p2.x - p1.x); A[1].y = p1.y + wx * (p2.y - p1.y);
        A[2].x = p2.x + wx * (p3.x - p2.x); A[2].y = p2.y + wx * (p3.y - p2.y);
        if (ty > 0) {
#pragma unroll
            for (int jx = 0; jx < 3; jx++) {
                out9[(ty - 1) * 3 + jx].x = Ap[jx].x + wy * (A[jx].x - Ap[jx].x);
                out9[(ty - 1) * 3 + jx].y = Ap[jx].y + wy * (A[jx].y - Ap[jx].y);
            }
        }
#pragma unroll
        for (int jx = 0; jx < 3; jx++) Ap[jx] = A[jx];
    }
}

// xy-lerped plane for attn2 (6x6 lattice, disjoint pairs)
__device__ __forceinline__ void plane6(const __half2* __restrict__ kv, int zoff,
                                       const int* LYo, const int* LXo,
                                       float wx, float wy, float2* out9)
{
#pragma unroll
    for (int u = 0; u < 3; u++) {
        float2 A0[3], A1[3];
#pragma unroll
        for (int jx = 0; jx < 3; jx++) {
            float2 a = __half22float2(kv[zoff + LYo[2 * u] + LXo[2 * jx]]);
            float2 c = __half22float2(kv[zoff + LYo[2 * u] + LXo[2 * jx + 1]]);
            A0[jx].x = a.x + wx * (c.x - a.x); A0[jx].y = a.y + wx * (c.y - a.y);
        }
#pragma unroll
        for (int jx = 0; jx < 3; jx++) {
            float2 a = __half22float2(kv[zoff + LYo[2 * u + 1] + LXo[2 * jx]]);
            float2 c = __half22float2(kv[zoff + LYo[2 * u + 1] + LXo[2 * jx + 1]]);
            A1[jx].x = a.x + wx * (c.x - a.x); A1[jx].y = a.y + wx * (c.y - a.y);
        }
#pragma unroll
        for (int jx = 0; jx < 3; jx++) {
            out9[u * 3 + jx].x = A0[jx].x + wy * (A1[jx].x - A0[jx].x);
            out9[u * 3 + jx].y = A0[jx].y + wy * (A1[jx].y - A0[jx].y);
        }
    }
}

// shared end-phase: sc from sK, softmax with v from sV
__device__ __forceinline__ float attn_tail(const float* sK, const float* sV,
                                           const float* bias, float q)
{
    float sc[27];
#pragma unroll
    for (int j = 0; j < 27; j++) sc[j] = q * sK[j * 32];
#pragma unroll
    for (int o = 16; o; o >>= 1)
#pragma unroll
        for (int j = 0; j < 27; j++) sc[j] += __shfl_xor_sync(0xffffffffu, sc[j], o);
    float m = -1e30f;
#pragma unroll
    for (int j = 0; j < 27; j++) { sc[j] = sc[j] * SCALE + bias[j]; m = fmaxf(m, sc[j]); }
    float l = 0.f, acc = 0.f;
#pragma unroll
    for (int j = 0; j < 27; j++) {
        float p = __expf(sc[j] - m);
        l += p;
        acc += p * sV[j * 32];
    }
    return acc / l;
}

// ================= attention branch 0 (dil=1) =================
__global__ __launch_bounds__(128, 6) void k_attn1(const float* __restrict__ bias0)
{
    __shared__ float sK[AW][27][32];
    __shared__ float sV[AW][27][32];

    const int bhh = blockIdx.y;
    const int b = bhh / 3, hh = bhh % 3;
    const int h = hh;
    const int bh = b * NH + h;
    const float* bias = bias0 + hh * 27;

    const int lane = threadIdx.x & 31, wid = threadIdx.x >> 5;
    const int s0b = blockIdx.x * AW;
    const int s = s0b + wid;
    const int z = s >> 10, y = (s >> 5) & 31, x = s & 31;

    const size_t qi = ((size_t)bh * NS + s) * 32 + lane;
    const float q = g_qT[qi];
    const float* ob = g_offs + ((size_t)bh * NS + s) * 3;
    const float bx = (float)x + ob[0] * 15.5f;
    const float by = (float)y + ob[1] * 15.5f;
    const float bz = (float)z + ob[2] * 7.5f;

    const __half2* __restrict__ kv = g_kvh + (size_t)bh * NS * HD;

    float fx = floorf(bx), fy = floorf(by), fz = floorf(bz);
    int X0 = (int)fx, Y0 = (int)fy, Z0 = (int)fz;
    float wx = bx - fx, wy = by - fy, wz = bz - fz;
    float uz = 1.f - wz;

    int LXo[4], LYo[4], LZo[4];
#pragma unroll
    for (int t = 0; t < 4; t++) {
        LXo[t] = min(max(X0 - 1 + t, 0), 31) * 32 + lane;
        LYo[t] = min(max(Y0 - 1 + t, 0), 31) * 1024;
        LZo[t] = min(max(Z0 - 1 + t, 0), 15) * 32768;
    }

    float* myK = &sK[wid][0][lane];
    float* myV = &sV[wid][0][lane];

    float2 prev[9], cur[9];
    plane4(kv, LZo[0], LYo, LXo, wx, wy, prev);
#pragma unroll
    for (int j = 0; j < 3; j++) {
        plane4(kv, LZo[j + 1], LYo, LXo, wx, wy, cur);
#pragma unroll
        for (int r = 0; r < 9; r++) {
            myK[(j * 9 + r) * 32] = uz * prev[r].x + wz * cur[r].x;
            myV[(j * 9 + r) * 32] = uz * prev[r].y + wz * cur[r].y;
            prev[r] = cur[r];
        }
    }

    float res = attn_tail(myK, myV, bias, q);
    attn_epilogue(res, b, h, 0, lane, wid, s0b, qi);
}

// ================= attention branch 1 (dil=2) =================
__global__ __launch_bounds__(128, 6) void k_attn2(const float* __restrict__ bias1)
{
    __shared__ float sK[AW][27][32];
    __shared__ float sV[AW][27][32];

    const int bhh = blockIdx.y;
    const int b = bhh / 3, hh = bhh % 3;
    const int h = hh + 3;
    const int bh = b * NH + h;
    const float* bias = bias1 + hh * 27;

    const int lane = threadIdx.x & 31, wid = threadIdx.x >> 5;
    const int s0b = blockIdx.x * AW;
    const int s = s0b + wid;
    const int z = s >> 10, y = (s >> 5) & 31, x = s & 31;

    const size_t qi = ((size_t)bh * NS + s) * 32 + lane;
    const float q = g_qT[qi];
    const float* ob = g_offs + ((size_t)bh * NS + s) * 3;
    const float bx = (float)x + ob[0] * 15.5f;
    const float by = (float)y + ob[1] * 15.5f;
    const float bz = (float)z + ob[2] * 7.5f;

    const __half2* __restrict__ kv = g_kvh + (size_t)bh * NS * HD;

    float fx = floorf(bx), fy = floorf(by), fz = floorf(bz);
    int X0 = (int)fx, Y0 = (int)fy, Z0 = (int)fz;
    float wx = bx - fx, wy = by - fy, wz = bz - fz;
    float uz = 1.f - wz;

    int LXo[6], LYo[6], LZo[6];
#pragma unroll
    for (int t = 0; t < 6; t++) {
        LXo[t] = min(max(X0 - 2 + t, 0), 31) * 32 + lane;
        LYo[t] = min(max(Y0 - 2 + t, 0), 31) * 1024;
        LZo[t] = min(max(Z0 - 2 + t, 0), 15) * 32768;
    }

    float* myK = &sK[wid][0][lane];
    float* myV = &sV[wid][0][lane];

    float2 pa[9], pb[9];
#pragma unroll
    for (int j = 0; j < 3; j++) {
        plane6(kv, LZo[2 * j],     LYo, LXo, wx, wy, pa);
        plane6(kv, LZo[2 * j + 1], LYo, LXo, wx, wy, pb);
#pragma unroll
        for (int r = 0; r < 9; r++) {
            myK[(j * 9 + r) * 32] = uz * pa[r].x + wz * pb[r].x;
            myV[(j * 9 + r) * 32] = uz * pa[r].y + wz * pb[r].y;
        }
    }

    float res = attn_tail(myK, myV, bias, q);
    attn_epilogue(res, b, h, 1, lane, wid, s0b, qi);
}

// ================= final conv: g_attnC [b,c,s] x pw -> out [b,c,s] =================
__global__ __launch_bounds__(256) void k_gemm_final(const float* __restrict__ W,
                                                    const float* __restrict__ bias,
                                                    float* __restrict__ out)
{
    const int b  = blockIdx.z;
    const int o0 = blockIdx.y * 64;
    const int s0 = blockIdx.x * 128;
    const int tid = threadIdx.x;
    const int tx = tid & 15, ty = tid >> 4;

    __shared__ __align__(16) float sW[16][68];
    __shared__ __align__(16) float sX[16][136];

    float acc[4][8] = {};
    const float* Xb = g_attnC + (size_t)b * CH * NS;

    for (int kk = 0; kk < CH; kk += 16) {
        {
            int r = tid >> 2, cq = (tid & 3) * 4;
            float4 w4 = *(const float4*)&W[(o0 + r) * CH + kk + cq];
            sW[cq + 0][r] = w4.x; sW[cq + 1][r] = w4.y;
            sW[cq + 2][r] = w4.z; sW[cq + 3][r] = w4.w;
        }
        {
            int r = tid >> 4, sq = (tid & 15) * 8;
            *(float4*)&sX[r][sq]     = *(const float4*)&Xb[(size_t)(kk + r) * NS + s0 + sq];
            *(float4*)&sX[r][sq + 4] = *(const float4*)&Xb[(size_t)(kk + r) * NS + s0 + sq + 4];
        }
        __syncthreads();
#pragma unroll
        for (int k = 0; k < 16; k++) {
            float4 a  = *(const float4*)&sW[k][ty * 4];
            float4 b0 = *(const float4*)&sX[k][tx * 8];
            float4 b1 = *(const float4*)&sX[k][tx * 8 + 4];
            float av[4] = {a.x, a.y, a.z, a.w};
            float bv[8] = {b0.x, b0.y, b0.z, b0.w, b1.x, b1.y, b1.z, b1.w};
#pragma unroll
            for (int i = 0; i < 4; i++)
#pragma unroll
                for (int j = 0; j < 8; j++) acc[i][j] += av[i] * bv[j];
        }
        __syncthreads();
    }
#pragma unroll
    for (int i = 0; i < 4; i++) {
        int o = o0 + ty * 4 + i;
        float bv = bias[o];
        float4 r0 = make_float4(acc[i][0] + bv, acc[i][1] + bv, acc[i][2] + bv, acc[i][3] + bv);
        float4 r1 = make_float4(acc[i][4] + bv, acc[i][5] + bv, acc[i][6] + bv, acc[i][7] + bv);
        *(float4*)&out[O_OUT + ((size_t)b * CH + o) * NS + s0 + tx * 8]     = r0;
        *(float4*)&out[O_OUT + ((size_t)b * CH + o) * NS + s0 + tx * 8 + 4] = r1;
    }
}

__global__ void k_finalize(float* __restrict__ out)
{
    int t = threadIdx.x;
    const float inv_sp = 1.f / (float)NS;
    const float inv_en = 1.f / (3.f * 32.f * (float)NS);
    if (t < 12) out[O_MAG + t] = g_mag[t] * inv_sp;
    if (t < 4)  out[O_EN + t] = g_energy[t] * inv_en;
    if (t < 16) {
        int b = t >> 3, j = t & 7;
        out[O_GUIDE + t] = (j < 6) ? g_mag[b * 6 + j] * inv_sp
                                   : g_energy[b * 2 + (j - 6)] * inv_en;
    }
}

extern "C" void kernel_launch(void* const* d_in, const int* in_sizes, int n_in,
                              void* d_out, int out_size)
{
    const float* x    = (const float*)d_in[0];
    const float* qw   = (const float*)d_in[1];
    const float* qb   = (const float*)d_in[2];
    const float* kw   = (const float*)d_in[3];
    const float* kbi  = (const float*)d_in[4];
    const float* vw   = (const float*)d_in[5];
    const float* vbi  = (const float*)d_in[6];
    const float* pw   = (const float*)d_in[7];
    const float* pb   = (const float*)d_in[8];
    const float* odw  = (const float*)d_in[9];
    const float* odb  = (const float*)d_in[10];
    const float* lnw  = (const float*)d_in[11];
    const float* lnb  = (const float*)d_in[12];
    const float* opw  = (const float*)d_in[13];
    const float* opb  = (const float*)d_in[14];
    const float* rpew = (const float*)d_in[15];
    const float* rpeb = (const float*)d_in[16];
    const float* b0   = (const float*)d_in[17];
    const float* b1   = (const float*)d_in[18];
    float* out = (float*)d_out;

    k_zero<<<1, 32>>>();

    dim3 gG(NS / 128, CH / 64, Bc);
    k_gemm_q<<<gG, 256>>>(x, qw, qb);
    k_gemm_kv<<<gG, 256>>>(x, kw, kbi, vw, vbi);

    k_dwconv<<<dim3(NS / 64, Bc * NH), 256>>>(odw, odb, rpew, rpeb);
    k_offsets<<<dim3(Bc * NS / 8), 256>>>(lnw, lnb, opw, opb, out);

    k_attn1<<<dim3(NS / AW, Bc * 3), 128>>>(b0);
    k_attn2<<<dim3(NS / AW, Bc * 3), 128>>>(b1);

    k_gemm_final<<<gG, 256>>>(pw, pb, out);
    k_finalize<<<1, 32>>>(out);
}

// round 11
// speedup vs baseline: 1.0448x; 1.0448x over previous
#include <cuda_runtime.h>
#include <cuda_bf16.h>
#include <cuda_fp16.h>
#include <math.h>

#define Bc 2
#define NH 6
#define HD 32
#define Dz 16
#define Hy 32
#define Wx 32
#define NS (Dz*Hy*Wx)      // 16384
#define CH 192
#define SCALE 0.17677669529663687f

// Output regions (tuple concat): out, offs, offset_mag, branch_energy, guide
#define O_OUT   0
#define O_OFFS  6291456     // 2*192*16384
#define O_MAG   6881280     // + 2*6*16384*3
#define O_EN    6881292
#define O_GUIDE 6881296

// Scratch (device globals; allocation-free)
__device__ float   g_qT[Bc*NH*NS*HD];      // [bh][s][hd]
__device__ __half2 g_kvh[Bc*NH*NS*HD];     // [bh][s][hd] -> (k, v) fp16
__device__ float   g_tT[Bc*NH*NS*HD];
__device__ float   g_lepeT[Bc*NH*NS*HD];
__device__ float   g_attnC[Bc*CH*NS];      // [b][c][s]  (attn + lepe)
__device__ float   g_offs[Bc*NH*NS*3];
__device__ float   g_mag[Bc*NH];
__device__ float   g_energy[Bc*2];

__device__ __forceinline__ float warpSum(float v) {
#pragma unroll
    for (int o = 16; o; o >>= 1) v += __shfl_xor_sync(0xffffffffu, v, o);
    return v;
}

__global__ void k_zero() {
    int t = threadIdx.x;
    if (t < Bc*NH) g_mag[t] = 0.f;
    if (t < Bc*2)  g_energy[t] = 0.f;
}

// ================= GEMM: q conv  X[b,c,s] x qw -> g_qT [bh][s][hd] =================
// tile: 64 out x 128 s, 256 threads, per-thread 4o x 8s
__global__ __launch_bounds__(256) void k_gemm_q(const float* __restrict__ X,
                                                const float* __restrict__ W,
                                                const float* __restrict__ bias)
{
    const int b  = blockIdx.z;
    const int o0 = blockIdx.y * 64;
    const int s0 = blockIdx.x * 128;
    const int tid = threadIdx.x;
    const int tx = tid & 15, ty = tid >> 4;

    __shared__ __align__(16) float sW[16][68];    // [c][o]
    __shared__ __align__(16) float sX[16][136];   // [c][s]
    __shared__ float sC[64][129];

    float acc[4][8] = {};
    const float* Xb = X + (size_t)b * CH * NS;

    for (int kk = 0; kk < CH; kk += 16) {
        {
            int r = tid >> 2, cq = (tid & 3) * 4;
            float4 w4 = *(const float4*)&W[(o0 + r) * CH + kk + cq];
            sW[cq + 0][r] = w4.x; sW[cq + 1][r] = w4.y;
            sW[cq + 2][r] = w4.z; sW[cq + 3][r] = w4.w;
        }
        {
            int r = tid >> 4, sq = (tid & 15) * 8;
            *(float4*)&sX[r][sq]     = *(const float4*)&Xb[(size_t)(kk + r) * NS + s0 + sq];
            *(float4*)&sX[r][sq + 4] = *(const float4*)&Xb[(size_t)(kk + r) * NS + s0 + sq + 4];
        }
        __syncthreads();
#pragma unroll
        for (int k = 0; k < 16; k++) {
            float4 a  = *(const float4*)&sW[k][ty * 4];
            float4 b0 = *(const float4*)&sX[k][tx * 8];
            float4 b1 = *(const float4*)&sX[k][tx * 8 + 4];
            float av[4] = {a.x, a.y, a.z, a.w};
            float bv[8] = {b0.x, b0.y, b0.z, b0.w, b1.x, b1.y, b1.z, b1.w};
#pragma unroll
            for (int i = 0; i < 4; i++)
#pragma unroll
                for (int j = 0; j < 8; j++) acc[i][j] += av[i] * bv[j];
        }
        __syncthreads();
    }
#pragma unroll
    for (int i = 0; i < 4; i++) {
        float bv = bias[o0 + ty * 4 + i];
#pragma unroll
        for (int j = 0; j < 8; j++) sC[ty * 4 + i][tx * 8 + j] = acc[i][j] + bv;
    }
    __syncthreads();
#pragma unroll
    for (int it = 0; it < 32; ++it) {
        int idx = tid + it * 256;
        int ol = idx & 63, sl = idx >> 6;
        int o = o0 + ol;
        g_qT[(((size_t)b * NH + (o >> 5)) * NS + (s0 + sl)) * HD + (o & 31)] = sC[ol][sl];
    }
}

// ================= GEMM: fused k & v conv -> g_kvh half2 =================
__global__ __launch_bounds__(256) void k_gemm_kv(const float* __restrict__ X,
                                                 const float* __restrict__ Wk, const float* __restrict__ bk,
                                                 const float* __restrict__ Wv, const float* __restrict__ bv_)
{
    const int b  = blockIdx.z;
    const int o0 = blockIdx.y * 64;
    const int s0 = blockIdx.x * 128;
    const int tid = threadIdx.x;
    const int tx = tid & 15, ty = tid >> 4;

    __shared__ __align__(16) float sWk[16][68];
    __shared__ __align__(16) float sWv[16][68];
    __shared__ __align__(16) float sX[16][136];
    __shared__ __half2 sC2[64][133];

    float ak[4][8] = {}, av_[4][8] = {};
    const float* Xb = X + (size_t)b * CH * NS;

    for (int kk = 0; kk < CH; kk += 16) {
        {
            int r = tid >> 2, cq = (tid & 3) * 4;
            float4 w4 = *(const float4*)&Wk[(o0 + r) * CH + kk + cq];
            sWk[cq + 0][r] = w4.x; sWk[cq + 1][r] = w4.y; sWk[cq + 2][r] = w4.z; sWk[cq + 3][r] = w4.w;
            float4 v4 = *(const float4*)&Wv[(o0 + r) * CH + kk + cq];
            sWv[cq + 0][r] = v4.x; sWv[cq + 1][r] = v4.y; sWv[cq + 2][r] = v4.z; sWv[cq + 3][r] = v4.w;
        }
        {
            int r = tid >> 4, sq = (tid & 15) * 8;
            *(float4*)&sX[r][sq]     = *(const float4*)&Xb[(size_t)(kk + r) * NS + s0 + sq];
            *(float4*)&sX[r][sq + 4] = *(const float4*)&Xb[(size_t)(kk + r) * NS + s0 + sq + 4];
        }
        __syncthreads();
#pragma unroll
        for (int k = 0; k < 16; k++) {
            float4 wa = *(const float4*)&sWk[k][ty * 4];
            float4 wb = *(const float4*)&sWv[k][ty * 4];
            float4 b0 = *(const float4*)&sX[k][tx * 8];
            float4 b1 = *(const float4*)&sX[k][tx * 8 + 4];
            float wav[4] = {wa.x, wa.y, wa.z, wa.w};
            float wbv[4] = {wb.x, wb.y, wb.z, wb.w};
            float xv[8] = {b0.x, b0.y, b0.z, b0.w, b1.x, b1.y, b1.z, b1.w};
#pragma unroll
            for (int i = 0; i < 4; i++)
#pragma unroll
                for (int j = 0; j < 8; j++) {
                    ak[i][j]  += wav[i] * xv[j];
                    av_[i][j] += wbv[i] * xv[j];
                }
        }
        __syncthreads();
    }
#pragma unroll
    for (int i = 0; i < 4; i++) {
        int o = o0 + ty * 4 + i;
        float bkk = bk[o], bvv = bv_[o];
#pragma unroll
        for (int j = 0; j < 8; j++)
            sC2[ty * 4 + i][tx * 8 + j] = __floats2half2_rn(ak[i][j] + bkk, av_[i][j] + bvv);
    }
    __syncthreads();
#pragma unroll
    for (int it = 0; it < 32; ++it) {
        int idx = tid + it * 256;
        int ol = idx & 63, sl = idx >> 6;
        int o = o0 + ol;
        g_kvh[(((size_t)b * NH + (o >> 5)) * NS + (s0 + sl)) * HD + (o & 31)] = sC2[ol][sl];
    }
}

// ================= depthwise 3x3x3 on qT -> tT & lepeT (x-register-blocked) =================
__global__ __launch_bounds__(256) void k_dwconv(const float* __restrict__ odw, const float* __restrict__ odb,
                                                const float* __restrict__ rpew, const float* __restrict__ rpeb)
{
    const int bh = blockIdx.y;
    const int h = bh % NH;
    const int lane = threadIdx.x & 31, wid = threadIdx.x >> 5;

    __shared__ float sWt[27][32];
    __shared__ float sWl[27][32];
    for (int idx = threadIdx.x; idx < 27 * 32; idx += 256) {
        int c = idx & 31, tap = idx >> 5;
        sWt[tap][c] = odw[(h * 32 + c) * 27 + tap];
        sWl[tap][c] = rpew[(h * 32 + c) * 27 + tap];
    }
    __syncthreads();

    const float bt = odb[h * 32 + lane];
    const float bl = rpeb[h * 32 + lane];
    const float* base = g_qT + (size_t)bh * NS * HD;

    const int s0 = blockIdx.x * 64 + wid * 8;
    const int z = s0 >> 10, y = (s0 >> 5) & 31, xb = s0 & 31;

    float at[8], al[8];
#pragma unroll
    for (int p = 0; p < 8; p++) { at[p] = bt; al[p] = bl; }

#pragma unroll
    for (int kd = 0; kd < 3; kd++) {
        int zz = z + kd - 1;
        if ((unsigned)zz >= (unsigned)Dz) continue;
#pragma unroll
        for (int kh = 0; kh < 3; kh++) {
            int yy = y + kh - 1;
            if ((unsigned)yy >= (unsigned)Hy) continue;
            const float* rowp = base + (size_t)(zz * 1024 + yy * 32) * 32 + lane;
            float w[10];
#pragma unroll
            for (int i = 0; i < 10; i++) {
                int xx = xb - 1 + i;
                w[i] = ((unsigned)xx < (unsigned)Wx) ? rowp[xx * 32] : 0.f;
            }
            const int t0 = (kd * 3 + kh) * 3;
            const float wt0 = sWt[t0][lane], wt1 = sWt[t0 + 1][lane], wt2 = sWt[t0 + 2][lane];
            const float wl0 = sWl[t0][lane], wl1 = sWl[t0 + 1][lane], wl2 = sWl[t0 + 2][lane];
#pragma unroll
            for (int p = 0; p < 8; p++) {
                at[p] += w[p] * wt0 + w[p + 1] * wt1 + w[p + 2] * wt2;
                al[p] += w[p] * wl0 + w[p + 1] * wl1 + w[p + 2] * wl2;
            }
        }
    }
#pragma unroll
    for (int p = 0; p < 8; p++) {
        size_t oi = ((size_t)bh * NS + s0 + p) * 32 + lane;
        g_tT[oi] = at[p];
        g_lepeT[oi] = al[p];
    }
}

// ================= LN + GELU + offset conv + tanh*scale =================
__global__ void k_offsets(const float* __restrict__ lnw, const float* __restrict__ lnb,
                          const float* __restrict__ opw, const float* __restrict__ opb,
                          float* __restrict__ d_out)
{
    __shared__ float sOp[18 * 192];
    __shared__ float sLn[2][192];
    for (int i = threadIdx.x; i < 18 * 192; i += 256) sOp[i] = opw[i];
    for (int i = threadIdx.x; i < 192; i += 256) { sLn[0][i] = lnw[i]; sLn[1][i] = lnb[i]; }
    __syncthreads();

    const int lane = threadIdx.x & 31, wid = threadIdx.x >> 5;
    const int gid = blockIdx.x * 8 + wid;
    const int b = gid >> 14;
    const int s = gid & (NS - 1);

    float v[6];
#pragma unroll
    for (int h = 0; h < 6; h++) v[h] = g_tT[(((size_t)b * 6 + h) * NS + s) * 32 + lane];

    float sm = 0.f;
#pragma unroll
    for (int h = 0; h < 6; h++) sm += v[h];
    sm = warpSum(sm);
    float mean = sm * (1.f / 192.f);
    float s2 = 0.f;
#pragma unroll
    for (int h = 0; h < 6; h++) { float d = v[h] - mean; s2 += d * d; }
    s2 = warpSum(s2);
    float inv = rsqrtf(s2 * (1.f / 192.f) + 1e-5f);

    float g[6];
#pragma unroll
    for (int h = 0; h < 6; h++) {
        int c = h * 32 + lane;
        float n = (v[h] - mean) * inv * sLn[0][c] + sLn[1][c];
        g[h] = 0.5f * n * (1.f + erff(n * 0.70710678118654752f));
    }

    float p18[18];
#pragma unroll
    for (int o = 0; o < 18; o++) {
        float p = 0.f;
#pragma unroll
        for (int h = 0; h < 6; h++) p += g[h] * sOp[o * 192 + h * 32 + lane];
        p18[o] = p;
    }
#pragma unroll
    for (int o = 16; o; o >>= 1)
#pragma unroll
        for (int j = 0; j < 18; j++) p18[j] += __shfl_xor_sync(0xffffffffu, p18[j], o);

    float mine = 0.f;
#pragma unroll
    for (int j = 0; j < 18; j++) if (lane == j) mine = p18[j];

    float ov = 0.f;
    if (lane < 18) {
        float val = tanhf(mine + opb[lane]);
        int comp = lane % 3;
        float sc = (comp == 2) ? (2.f / 15.f) : (2.f / 31.f);
        ov = val * sc;
        int h = lane / 3;
        size_t oi = (((size_t)b * 6 + h) * NS + s) * 3 + comp;
        g_offs[oi] = ov;
        d_out[O_OFFS + oi] = ov;
    }
    float ox = __shfl_sync(0xffffffffu, ov, (lane < 6) ? 3 * lane : 0);
    float oy = __shfl_sync(0xffffffffu, ov, (lane < 6) ? 3 * lane + 1 : 0);
    float oz = __shfl_sync(0xffffffffu, ov, (lane < 6) ? 3 * lane + 2 : 0);
    if (lane < 6) atomicAdd(&g_mag[b * 6 + lane], sqrtf(ox * ox + oy * oy + oz * oz));
}

// ================= attention epilogue (8 warps) =================
__device__ __forceinline__ void attn_epilogue(float res, int b, int h, int bi,
                                              int lane, int wid, int s0b, size_t qi)
{
    float outv = res + g_lepeT[qi];
    __shared__ float sT[8][33];
    __shared__ float sE[8];
    sT[wid][lane] = outv;
    float e = warpSum(fabsf(res));
    if (lane == 0) sE[wid] = e;
    __syncthreads();
    int ch = threadIdx.x >> 3, si = threadIdx.x & 7;
    g_attnC[((size_t)b * CH + h * 32 + ch) * NS + s0b + si] = sT[si][ch];
    if (threadIdx.x == 0) {
        float t = 0.f;
#pragma unroll
        for (int i = 0; i < 8; i++) t += sE[i];
        atomicAdd(&g_energy[b * 2 + bi], t);
    }
}

// ================= shared softmax tail over 27 (sc partials, val.y payload) =========
__device__ __forceinline__ float softmax27(float* sc, const float2* zacc, const float* bias)
{
#pragma unroll
    for (int o = 16; o; o >>= 1)
#pragma unroll
        for (int j = 0; j < 27; j++) sc[j] += __shfl_xor_sync(0xffffffffu, sc[j], o);
    float m = -1e30f;
#pragma unroll
    for (int j = 0; j < 27; j++) { sc[j] = sc[j] * SCALE + bias[j]; m = fmaxf(m, sc[j]); }
    float l = 0.f, acc = 0.f;
#pragma unroll
    for (int j = 0; j < 27; j++) {
        float p = __expf(sc[j] - m);
        l += p;
        acc += p * zacc[j].y;
    }
    return acc / l;
}

// ================= attention branch 0 (dil=1): shared 4x4x4 lattice =================
__global__ __launch_bounds__(256) void k_attn1(const float* __restrict__ bias0)
{
    const int bhh = blockIdx.y;
    const int b = bhh / 3, hh = bhh % 3;
    const int h = hh;
    const int bh = b * NH + h;
    const float* bias = bias0 + hh * 27;

    const int lane = threadIdx.x & 31, wid = threadIdx.x >> 5;
    const int s0b = blockIdx.x * 8;
    const int s = s0b + wid;
    const int z = s >> 10, y = (s >> 5) & 31, x = s & 31;

    const size_t qi = ((size_t)bh * NS + s) * 32 + lane;
    const float q = g_qT[qi];
    const float* ob = g_offs + ((size_t)bh * NS + s) * 3;
    const float bx = (float)x + ob[0] * 15.5f;
    const float by = (float)y + ob[1] * 15.5f;
    const float bz = (float)z + ob[2] * 7.5f;

    const __half2* __restrict__ kv = g_kvh + (size_t)bh * NS * HD;

    float fx = floorf(bx), fy = floorf(by), fz = floorf(bz);
    int X0 = (int)fx, Y0 = (int)fy, Z0 = (int)fz;
    float wx = bx - fx, wy = by - fy, wz = bz - fz;
    float uz = 1.f - wz;

    int LXo[4], LYo[4], LZo[4];
#pragma unroll
    for (int t = 0; t < 4; t++) {
        LXo[t] = min(max(X0 - 1 + t, 0), 31) * 32 + lane;
        LYo[t] = min(max(Y0 - 1 + t, 0), 31) * 1024;
        LZo[t] = min(max(Z0 - 1 + t, 0), 15) * 32768;
    }

    float2 zacc[27];
#pragma unroll
    for (int j = 0; j < 27; j++) zacc[j] = make_float2(0.f, 0.f);

#pragma unroll
    for (int tz = 0; tz < 4; tz++) {
        float2 P[4][4];
#pragma unroll
        for (int ty = 0; ty < 4; ty++)
#pragma unroll
            for (int tx = 0; tx < 4; tx++)
                P[ty][tx] = __half22float2(kv[LZo[tz] + LYo[ty] + LXo[tx]]);
        float2 A[4][3];
#pragma unroll
        for (int ty = 0; ty < 4; ty++)
#pragma unroll
            for (int jx = 0; jx < 3; jx++) {
                A[ty][jx].x = P[ty][jx].x + wx * (P[ty][jx + 1].x - P[ty][jx].x);
                A[ty][jx].y = P[ty][jx].y + wx * (P[ty][jx + 1].y - P[ty][jx].y);
            }
        float2 Bv[3][3];
#pragma unroll
        for (int jy = 0; jy < 3; jy++)
#pragma unroll
            for (int jx = 0; jx < 3; jx++) {
                Bv[jy][jx].x = A[jy][jx].x + wy * (A[jy + 1][jx].x - A[jy][jx].x);
                Bv[jy][jx].y = A[jy][jx].y + wy * (A[jy + 1][jx].y - A[jy][jx].y);
            }
        if (tz < 3) {
#pragma unroll
            for (int r = 0; r < 9; r++) {
                zacc[tz * 9 + r].x += uz * Bv[r / 3][r % 3].x;
                zacc[tz * 9 + r].y += uz * Bv[r / 3][r % 3].y;
            }
        }
        if (tz > 0) {
#pragma unroll
            for (int r = 0; r < 9; r++) {
                zacc[(tz - 1) * 9 + r].x += wz * Bv[r / 3][r % 3].x;
                zacc[(tz - 1) * 9 + r].y += wz * Bv[r / 3][r % 3].y;
            }
        }
    }

    float sc[27];
#pragma unroll
    for (int j = 0; j < 27; j++) sc[j] = q * zacc[j].x;
    float res = softmax27(sc, zacc, bias);
    attn_epilogue(res, b, h, 0, lane, wid, s0b, qi);
}

// ============ attention branch 1 (dil=2): separable disjoint 6x6x6 lattice ============
__global__ __launch_bounds__(256) void k_attn2(const float* __restrict__ bias1)
{
    const int bhh = blockIdx.y;
    const int b = bhh / 3, hh = bhh % 3;
    const int h = hh + 3;
    const int bh = b * NH + h;
    const float* bias = bias1 + hh * 27;

    const int lane = threadIdx.x & 31, wid = threadIdx.x >> 5;
    const int s0b = blockIdx.x * 8;
    const int s = s0b + wid;
    const int z = s >> 10, y = (s >> 5) & 31, x = s & 31;

    const size_t qi = ((size_t)bh * NS + s) * 32 + lane;
    const float q = g_qT[qi];
    const float* ob = g_offs + ((size_t)bh * NS + s) * 3;
    const float bx = (float)x + ob[0] * 15.5f;
    const float by = (float)y + ob[1] * 15.5f;
    const float bz = (float)z + ob[2] * 7.5f;

    const __half2* __restrict__ kv = g_kvh + (size_t)bh * NS * HD;

    float fx = floorf(bx), fy = floorf(by), fz = floorf(bz);
    int X0 = (int)fx, Y0 = (int)fy, Z0 = (int)fz;
    float wx = bx - fx, wy = by - fy, wz = bz - fz;
    float uz = 1.f - wz;

    int LXo[6], LYo[6], LZo[6];
#pragma unroll
    for (int t = 0; t < 6; t++) {
        LXo[t] = min(max(X0 - 2 + t, 0), 31) * 32 + lane;
        LYo[t] = min(max(Y0 - 2 + t, 0), 31) * 1024;
        LZo[t] = min(max(Z0 - 2 + t, 0), 15) * 32768;
    }

    float2 zacc[27];
#pragma unroll
    for (int j = 0; j < 27; j++) zacc[j] = make_float2(0.f, 0.f);

#pragma unroll
    for (int tz = 0; tz < 6; tz++) {
        float2 A[6][3];
#pragma unroll
        for (int ty = 0; ty < 6; ty++)
#pragma unroll
            for (int jx = 0; jx < 3; jx++) {
                float2 a = __half22float2(kv[LZo[tz] + LYo[ty] + LXo[2 * jx]]);
                float2 c = __half22float2(kv[LZo[tz] + LYo[ty] + LXo[2 * jx + 1]]);
                A[ty][jx].x = a.x + wx * (c.x - a.x);
                A[ty][jx].y = a.y + wx * (c.y - a.y);
            }
        float2 Bv[3][3];
#pragma unroll
        for (int jy = 0; jy < 3; jy++)
#pragma unroll
            for (int jx = 0; jx < 3; jx++) {
                Bv[jy][jx].x = A[2 * jy][jx].x + wy * (A[2 * jy + 1][jx].x - A[2 * jy][jx].x);
                Bv[jy][jx].y = A[2 * jy][jx].y + wy * (A[2 * jy + 1][jx].y - A[2 * jy][jx].y);
            }
        const int jz = tz >> 1;
        const float wzz = (tz & 1) ? wz : uz;
#pragma unroll
        for (int r = 0; r < 9; r++) {
            zacc[jz * 9 + r].x += wzz * Bv[r / 3][r % 3].x;
            zacc[jz * 9 + r].y += wzz * Bv[r / 3][r % 3].y;
        }
    }

    float sc[27];
#pragma unroll
    for (int j = 0; j < 27; j++) sc[j] = q * zacc[j].x;
    float res = softmax27(sc, zacc, bias);
    attn_epilogue(res, b, h, 1, lane, wid, s0b, qi);
}

// ================= final conv: g_attnC [b,c,s] x pw -> out [b,c,s] =================
__global__ __launch_bounds__(256) void k_gemm_final(const float* __restrict__ W,
                                                    const float* __restrict__ bias,
                                                    float* __restrict__ out)
{
    const int b  = blockIdx.z;
    const int o0 = blockIdx.y * 64;
    const int s0 = blockIdx.x * 128;
    const int tid = threadIdx.x;
    const int tx = tid & 15, ty = tid >> 4;

    __shared__ __align__(16) float sW[16][68];
    __shared__ __align__(16) float sX[16][136];

    float acc[4][8] = {};
    const float* Xb = g_attnC + (size_t)b * CH * NS;

    for (int kk = 0; kk < CH; kk += 16) {
        {
            int r = tid >> 2, cq = (tid & 3) * 4;
            float4 w4 = *(const float4*)&W[(o0 + r) * CH + kk + cq];
            sW[cq + 0][r] = w4.x; sW[cq + 1][r] = w4.y;
            sW[cq + 2][r] = w4.z; sW[cq + 3][r] = w4.w;
        }
        {
            int r = tid >> 4, sq = (tid & 15) * 8;
            *(float4*)&sX[r][sq]     = *(const float4*)&Xb[(size_t)(kk + r) * NS + s0 + sq];
            *(float4*)&sX[r][sq + 4] = *(const float4*)&Xb[(size_t)(kk + r) * NS + s0 + sq + 4];
        }
        __syncthreads();
#pragma unroll
        for (int k = 0; k < 16; k++) {
            float4 a  = *(const float4*)&sW[k][ty * 4];
            float4 b0 = *(const float4*)&sX[k][tx * 8];
            float4 b1 = *(const float4*)&sX[k][tx * 8 + 4];
            float av[4] = {a.x, a.y, a.z, a.w};
            float bv[8] = {b0.x, b0.y, b0.z, b0.w, b1.x, b1.y, b1.z, b1.w};
#pragma unroll
            for (int i = 0; i < 4; i++)
#pragma unroll
                for (int j = 0; j < 8; j++) acc[i][j] += av[i] * bv[j];
        }
        __syncthreads();
    }
#pragma unroll
    for (int i = 0; i < 4; i++) {
        int o = o0 + ty * 4 + i;
        float bv = bias[o];
        float4 r0 = make_float4(acc[i][0] + bv, acc[i][1] + bv, acc[i][2] + bv, acc[i][3] + bv);
        float4 r1 = make_float4(acc[i][4] + bv, acc[i][5] + bv, acc[i][6] + bv, acc[i][7] + bv);
        *(float4*)&out[O_OUT + ((size_t)b * CH + o) * NS + s0 + tx * 8]     = r0;
        *(float4*)&out[O_OUT + ((size_t)b * CH + o) * NS + s0 + tx * 8 + 4] = r1;
    }
}

__global__ void k_finalize(float* __restrict__ out)
{
    int t = threadIdx.x;
    const float inv_sp = 1.f / (float)NS;
    const float inv_en = 1.f / (3.f * 32.f * (float)NS);
    if (t < 12) out[O_MAG + t] = g_mag[t] * inv_sp;
    if (t < 4)  out[O_EN + t] = g_energy[t] * inv_en;
    if (t < 16) {
        int b = t >> 3, j = t & 7;
        out[O_GUIDE + t] = (j < 6) ? g_mag[b * 6 + j] * inv_sp
                                   : g_energy[b * 2 + (j - 6)] * inv_en;
    }
}

extern "C" void kernel_launch(void* const* d_in, const int* in_sizes, int n_in,
                              void* d_out, int out_size)
{
    const float* x    = (const float*)d_in[0];
    const float* qw   = (const float*)d_in[1];
    const float* qb   = (const float*)d_in[2];
    const float* kw   = (const float*)d_in[3];
    const float* kbi  = (const float*)d_in[4];
    const float* vw   = (const float*)d_in[5];
    const float* vbi  = (const float*)d_in[6];
    const float* pw   = (const float*)d_in[7];
    const float* pb   = (const float*)d_in[8];
    const float* odw  = (const float*)d_in[9];
    const float* odb  = (const float*)d_in[10];
    const float* lnw  = (const float*)d_in[11];
    const float* lnb  = (const float*)d_in[12];
    const float* opw  = (const float*)d_in[13];
    const float* opb  = (const float*)d_in[14];
    const float* rpew = (const float*)d_in[15];
    const float* rpeb = (const float*)d_in[16];
    const float* b0   = (const float*)d_in[17];
    const float* b1   = (const float*)d_in[18];
    float* out = (float*)d_out;

    k_zero<<<1, 32>>>();

    dim3 gG(NS / 128, CH / 64, Bc);
    k_gemm_q<<<gG, 256>>>(x, qw, qb);
    k_gemm_kv<<<gG, 256>>>(x, kw, kbi, vw, vbi);

    k_dwconv<<<dim3(NS / 64, Bc * NH), 256>>>(odw, odb, rpew, rpeb);
    k_offsets<<<dim3(Bc * NS / 8), 256>>>(lnw, lnb, opw, opb, out);

    k_attn1<<<dim3(NS / 8, Bc * 3), 256>>>(b0);
    k_attn2<<<dim3(NS / 8, Bc * 3), 256>>>(b1);

    k_gemm_final<<<gG, 256>>>(pw, pb, out);
    k_finalize<<<1, 32>>>(out);
}